// round 2
// baseline (speedup 1.0000x reference)
#include <cuda_runtime.h>
#include <cuda_bf16.h>

#define B_ 256
#define N_ 512
#define M_ 1024

typedef unsigned long long u64;
typedef unsigned int u32;

// Prescaled logits: logits * log2(e), computed by a preamble kernel each launch.
__device__ float g_lscaled[N_ * M_];

__global__ void prescale_logits_kernel(const float* __restrict__ logits) {
    int i = blockIdx.x * blockDim.x + threadIdx.x;
    if (i < N_ * M_) g_lscaled[i] = logits[i] * 1.4426950408889634f;
}

// ---- packed f32x2 helpers (sm_103a FFMA2 path, PTX-only) ----
__device__ __forceinline__ u64 fma2(u64 a, u64 b, u64 c) {
    u64 d; asm("fma.rn.f32x2 %0, %1, %2, %3;" : "=l"(d) : "l"(a), "l"(b), "l"(c));
    return d;
}
__device__ __forceinline__ u64 add2(u64 a, u64 b) {
    u64 d; asm("add.rn.f32x2 %0, %1, %2;" : "=l"(d) : "l"(a), "l"(b));
    return d;
}
__device__ __forceinline__ u64 pack2(u32 lo, u32 hi) {
    u64 d; asm("mov.b64 %0, {%1, %2};" : "=l"(d) : "r"(lo), "r"(hi));
    return d;
}
__device__ __forceinline__ void unpack2(u64 v, u32& lo, u32& hi) {
    asm("mov.b64 {%0, %1}, %2;" : "=r"(lo), "=r"(hi) : "l"(v));
}
__device__ __forceinline__ u64 bcast2(float f) {
    u32 b = __float_as_uint(f);
    return (((u64)b) << 32) | (u64)b;
}

union F4U2 { float4 f4; u64 u2[2]; };

// Packed exp2 of two floats already in log2 domain.
// Magic-round: tsh = t + (2^23+2^22) puts round(t) in the low mantissa bits;
// (bits << 23) mod 2^32 == ni << 23 because the low 9 bits of 0x4B400000 are 0,
// so adding it to the poly's float bits is an exact ldexp.
struct Exp2Consts {
    u64 MAGIC2, NMAGIC2, MONE2, ONE2, C4, C3, C2, C1;
};

__device__ __forceinline__ u64 exp2pair(u64 t, const Exp2Consts& k) {
    u64 tsh = add2(t, k.MAGIC2);
    u64 r   = add2(tsh, k.NMAGIC2);        // rounded integer value, as float pair
    u64 f   = fma2(r, k.MONE2, t);         // f = t - r, f in [-0.5, 0.5]
    u64 p   = fma2(f, k.C4, k.C3);         // degree-4 Taylor of 2^f
    p = fma2(f, p, k.C2);
    p = fma2(f, p, k.C1);
    p = fma2(f, p, k.ONE2);
    u32 tlo, thi, plo, phi;
    unpack2(tsh, tlo, thi);
    unpack2(p,   plo, phi);
    return pack2(plo + (tlo << 23), phi + (thi << 23));
}

__global__ __launch_bounds__(256) void gsm_kernel(
    const float* __restrict__ x,      // [B, M]
    const float* __restrict__ gum,    // [B, N, M]
    float* __restrict__ out)          // [B, N]
{
    const int warp = blockIdx.x * (blockDim.x >> 5) + (threadIdx.x >> 5);
    const int lane = threadIdx.x & 31;
    const int b = warp >> 9;          // / N_
    const int n = warp & (N_ - 1);    // % N_

    const float4* __restrict__ g4 = (const float4*)(gum + (size_t)warp * M_) + lane;
    const float4* __restrict__ l4 = (const float4*)(g_lscaled + (size_t)n * M_) + lane;
    const float4* __restrict__ x4 = (const float4*)(x + (size_t)b * M_) + lane;

    Exp2Consts k;
    k.MAGIC2  = bcast2(12582912.0f);       // 2^23 + 2^22
    k.NMAGIC2 = bcast2(-12582912.0f);
    k.MONE2   = bcast2(-1.0f);
    k.ONE2    = bcast2(1.0f);
    k.C4      = bcast2(0.0096297515f);     // ln2^4/24
    k.C3      = bcast2(0.0555041087f);     // ln2^3/6
    k.C2      = bcast2(0.2402265070f);     // ln2^2/2
    k.C1      = bcast2(0.6931471806f);     // ln2
    const u64 L2E2 = bcast2(1.4426950408889634f);

    u64 s2  = 0;   // packed {0.0f, 0.0f}
    u64 ws2 = 0;

    #pragma unroll
    for (int it = 0; it < 8; ++it) {
        F4U2 gv, lv, xv;
        gv.f4 = g4[it * 32];
        lv.f4 = l4[it * 32];
        xv.f4 = x4[it * 32];

        u64 t0 = fma2(gv.u2[0], L2E2, lv.u2[0]);
        u64 t1 = fma2(gv.u2[1], L2E2, lv.u2[1]);
        u64 e0 = exp2pair(t0, k);
        u64 e1 = exp2pair(t1, k);

        s2  = add2(s2, e0);
        ws2 = fma2(e0, xv.u2[0], ws2);
        s2  = add2(s2, e1);
        ws2 = fma2(e1, xv.u2[1], ws2);
    }

    // collapse packed lanes
    u32 alo, ahi;
    unpack2(s2, alo, ahi);
    float s = __uint_as_float(alo) + __uint_as_float(ahi);
    unpack2(ws2, alo, ahi);
    float ws = __uint_as_float(alo) + __uint_as_float(ahi);

    // warp reduction
    #pragma unroll
    for (int o = 16; o > 0; o >>= 1) {
        s  += __shfl_xor_sync(0xFFFFFFFFu, s, o);
        ws += __shfl_xor_sync(0xFFFFFFFFu, ws, o);
    }

    if (lane == 0) out[warp] = __fdividef(ws, s);
}

extern "C" void kernel_launch(void* const* d_in, const int* in_sizes, int n_in,
                              void* d_out, int out_size) {
    // Identify inputs by element count (all three distinct):
    //   input  [B, M]    = 262144
    //   logits [N, M]    = 524288
    //   gumbel [B, N, M] = 134217728
    const float* x = nullptr;
    const float* logits = nullptr;
    const float* gum = nullptr;
    for (int i = 0; i < n_in; ++i) {
        if (in_sizes[i] == B_ * M_)       x      = (const float*)d_in[i];
        else if (in_sizes[i] == N_ * M_)  logits = (const float*)d_in[i];
        else                              gum    = (const float*)d_in[i];
    }

    prescale_logits_kernel<<<(N_ * M_ + 255) / 256, 256>>>(logits);

    const int rows = B_ * N_;                 // 131072 warps
    gsm_kernel<<<rows / 8, 256>>>(x, gum, (float*)d_out);
}

// round 3
// speedup vs baseline: 1.4785x; 1.4785x over previous
#include <cuda_runtime.h>
#include <cuda_bf16.h>

#define B_ 256
#define N_ 512
#define M_ 1024

// Prescaled logits: logits * log2(e), computed by a preamble kernel each launch.
__device__ float g_lscaled[N_ * M_];

__global__ void prescale_logits_kernel(const float* __restrict__ logits) {
    int i = blockIdx.x * blockDim.x + threadIdx.x;
    if (i < N_ * M_) g_lscaled[i] = logits[i] * 1.4426950408889634f;
}

// Fast exp2: t in log2 domain. Magic-round (2^23+2^22) gives round(t) in the
// low mantissa bits; adding (bits<<23) to the poly's float bits is an exact
// ldexp because the low 9 bits of 0x4B400000 are zero.
__device__ __forceinline__ float exp2_fast(float t) {
    const float MAGIC = 12582912.0f;          // 2^23 + 2^22
    float tsh = t + MAGIC;
    int   bi  = __float_as_int(tsh);
    float f   = t - (tsh - MAGIC);            // f in [-0.5, 0.5]
    // degree-4 Taylor of 2^f, rel err ~4e-5 (25x under 1e-3 threshold)
    float p = fmaf(f, 0.0096181291f, 0.0555041087f);
    p = fmaf(f, p, 0.2402265070f);
    p = fmaf(f, p, 0.6931471806f);
    p = fmaf(f, p, 1.0f);
    return __int_as_float(__float_as_int(p) + (bi << 23));
}

__global__ __launch_bounds__(128, 8) void gsm_kernel(
    const float* __restrict__ x,      // [B, M]
    const float* __restrict__ gum,    // [B, N, M]
    float* __restrict__ out)          // [B, N]
{
    const int lane = threadIdx.x & 31;
    const int wg   = (blockIdx.x * blockDim.x + threadIdx.x) >> 5;
    const int total_warps = (gridDim.x * blockDim.x) >> 5;

    const int rows  = B_ * N_;
    const int chunk = (rows + total_warps - 1) / total_warps;
    const int row0  = wg * chunk;
    const int row1  = min(row0 + chunk, rows);

    const float L2E = 1.4426950408889634f;

    for (int row = row0; row < row1; ++row) {
        const int b = row >> 9;           // / N_
        const int n = row & (N_ - 1);     // % N_

        const float4* __restrict__ g4 = (const float4*)(gum + (size_t)row * M_) + lane;
        const float4* __restrict__ l4 = (const float4*)(g_lscaled + (size_t)n * M_) + lane;
        const float4* __restrict__ x4 = (const float4*)(x + (size_t)b * M_) + lane;

        // Hoist the entire row's DRAM stream: 8 outstanding LDG.128 per warp.
        // Evict-first so the gumbel stream doesn't pollute L2 (logits/x live there).
        float4 g[8];
        #pragma unroll
        for (int i = 0; i < 8; ++i) g[i] = __ldcs(&g4[i * 32]);

        float s = 0.0f, ws = 0.0f;
        #pragma unroll
        for (int i = 0; i < 8; ++i) {
            float4 lv = __ldg(&l4[i * 32]);   // L2-resident
            float4 xv = __ldg(&x4[i * 32]);   // L1-warm across the chunk

            float e0 = exp2_fast(fmaf(g[i].x, L2E, lv.x));
            float e1 = exp2_fast(fmaf(g[i].y, L2E, lv.y));
            float e2 = exp2_fast(fmaf(g[i].z, L2E, lv.z));
            float e3 = exp2_fast(fmaf(g[i].w, L2E, lv.w));

            s += e0; ws = fmaf(e0, xv.x, ws);
            s += e1; ws = fmaf(e1, xv.y, ws);
            s += e2; ws = fmaf(e2, xv.z, ws);
            s += e3; ws = fmaf(e3, xv.w, ws);
        }

        // warp reduction (two independent shfl chains interleave)
        #pragma unroll
        for (int o = 16; o > 0; o >>= 1) {
            s  += __shfl_xor_sync(0xFFFFFFFFu, s, o);
            ws += __shfl_xor_sync(0xFFFFFFFFu, ws, o);
        }

        if (lane == 0) out[row] = __fdividef(ws, s);
    }
}

extern "C" void kernel_launch(void* const* d_in, const int* in_sizes, int n_in,
                              void* d_out, int out_size) {
    // Identify inputs by element count (all three distinct):
    //   input  [B, M]    = 262144
    //   logits [N, M]    = 524288
    //   gumbel [B, N, M] = 134217728
    const float* x = nullptr;
    const float* logits = nullptr;
    const float* gum = nullptr;
    for (int i = 0; i < n_in; ++i) {
        if (in_sizes[i] == B_ * M_)       x      = (const float*)d_in[i];
        else if (in_sizes[i] == N_ * M_)  logits = (const float*)d_in[i];
        else                              gum    = (const float*)d_in[i];
    }

    prescale_logits_kernel<<<(N_ * M_ + 255) / 256, 256>>>(logits);

    // Persistent-ish: 1184 blocks (~8 per SM) x 128 threads = 4736 warps,
    // each owning a contiguous chunk of ~28 rows.
    gsm_kernel<<<1184, 128>>>(x, gum, (float*)d_out);
}

// round 4
// speedup vs baseline: 1.5000x; 1.0145x over previous
#include <cuda_runtime.h>
#include <cuda_bf16.h>

#define B_ 256
#define N_ 512
#define M_ 1024

// Prescaled logits: logits * log2(e), computed by a preamble kernel each launch.
__device__ float g_lscaled[N_ * M_];

__global__ void prescale_logits_kernel(const float* __restrict__ logits) {
    int i = blockIdx.x * blockDim.x + threadIdx.x;
    if (i < N_ * M_) g_lscaled[i] = logits[i] * 1.4426950408889634f;
}

// Fast exp2: t in log2 domain. Magic-round (2^23+2^22) gives round(t) in the
// low mantissa bits; adding (bits<<23) to the poly's float bits is an exact
// ldexp because the low 9 bits of 0x4B400000 are zero.
// Degree-3 poly with c4/c5 Chebyshev-economized into c0..c3:
// abs err ~8e-5 on f in [-0.5,0.5] -> output rel err ~1e-4 (threshold 1e-3).
__device__ __forceinline__ float exp2_fast(float t) {
    const float MAGIC = 12582912.0f;          // 2^23 + 2^22
    float tsh = t + MAGIC;
    int   bi  = __float_as_int(tsh);
    float f   = t - (tsh - MAGIC);            // f in [-0.5, 0.5]
    float p = fmaf(f, 0.05592078f, 0.24263103f);
    p = fmaf(f, p, 0.69312114f);
    p = fmaf(f, p, 0.99992486f);
    return __int_as_float(__float_as_int(p) + (bi << 23));
}

__device__ __forceinline__ void load_row(float4 g[8], const float* __restrict__ gum,
                                         int row, int lane) {
    const float4* __restrict__ g4 = (const float4*)(gum + (size_t)row * M_) + lane;
    #pragma unroll
    for (int i = 0; i < 8; ++i) g[i] = __ldcs(&g4[i * 32]);
}

__device__ __forceinline__ void compute_row(const float4 g[8],
                                            const float* __restrict__ x,
                                            float* __restrict__ out,
                                            int row, int lane) {
    const int b = row >> 9;           // / N_
    const int n = row & (N_ - 1);     // % N_
    const float4* __restrict__ l4 = (const float4*)(g_lscaled + (size_t)n * M_) + lane;
    const float4* __restrict__ x4 = (const float4*)(x + (size_t)b * M_) + lane;
    const float L2E = 1.4426950408889634f;

    float s = 0.0f, ws = 0.0f;
    #pragma unroll
    for (int i = 0; i < 8; ++i) {
        float4 lv = __ldg(&l4[i * 32]);   // L2-resident (2 MB table)
        float4 xv = __ldg(&x4[i * 32]);   // L1-warm across the chunk

        float e0 = exp2_fast(fmaf(g[i].x, L2E, lv.x));
        float e1 = exp2_fast(fmaf(g[i].y, L2E, lv.y));
        float e2 = exp2_fast(fmaf(g[i].z, L2E, lv.z));
        float e3 = exp2_fast(fmaf(g[i].w, L2E, lv.w));

        s += e0; ws = fmaf(e0, xv.x, ws);
        s += e1; ws = fmaf(e1, xv.y, ws);
        s += e2; ws = fmaf(e2, xv.z, ws);
        s += e3; ws = fmaf(e3, xv.w, ws);
    }

    #pragma unroll
    for (int o = 16; o > 0; o >>= 1) {
        s  += __shfl_xor_sync(0xFFFFFFFFu, s, o);
        ws += __shfl_xor_sync(0xFFFFFFFFu, ws, o);
    }
    if (lane == 0) out[row] = __fdividef(ws, s);
}

__global__ __launch_bounds__(128, 5) void gsm_kernel(
    const float* __restrict__ x,      // [B, M]
    const float* __restrict__ gum,    // [B, N, M]
    float* __restrict__ out)          // [B, N]
{
    const int lane = threadIdx.x & 31;
    const int wg   = (blockIdx.x * blockDim.x + threadIdx.x) >> 5;
    const int total_warps = (gridDim.x * blockDim.x) >> 5;

    const int rows  = B_ * N_;
    const int chunk = (rows + total_warps - 1) / total_warps;
    const int row0  = wg * chunk;
    const int row1  = min(row0 + chunk, rows);
    if (row0 >= row1) return;

    // Software pipeline: while computing row i (from one buffer), row i+1's
    // 8 LDG.128 are already in flight into the other buffer -> each warp keeps
    // ~8 DRAM loads outstanding continuously instead of bursting.
    float4 bufA[8], bufB[8];
    load_row(bufA, gum, row0, lane);

    int row = row0;
    for (;;) {
        // A live, prefetch into B
        {
            int nxt = min(row + 1, row1 - 1);
            load_row(bufB, gum, nxt, lane);
            compute_row(bufA, x, out, row, lane);
            if (++row >= row1) break;
        }
        // B live, prefetch into A
        {
            int nxt = min(row + 1, row1 - 1);
            load_row(bufA, gum, nxt, lane);
            compute_row(bufB, x, out, row, lane);
            if (++row >= row1) break;
        }
    }
}

extern "C" void kernel_launch(void* const* d_in, const int* in_sizes, int n_in,
                              void* d_out, int out_size) {
    // Identify inputs by element count (all three distinct):
    //   input  [B, M]    = 262144
    //   logits [N, M]    = 524288
    //   gumbel [B, N, M] = 134217728
    const float* x = nullptr;
    const float* logits = nullptr;
    const float* gum = nullptr;
    for (int i = 0; i < n_in; ++i) {
        if (in_sizes[i] == B_ * M_)       x      = (const float*)d_in[i];
        else if (in_sizes[i] == N_ * M_)  logits = (const float*)d_in[i];
        else                              gum    = (const float*)d_in[i];
    }

    prescale_logits_kernel<<<(N_ * M_ + 255) / 256, 256>>>(logits);

    // Persistent single wave: 148 SMs x 5 CTAs x 128 threads = 2960 warps,
    // each owning a contiguous chunk of ~45 rows.
    gsm_kernel<<<740, 128>>>(x, gum, (float*)d_out);
}